// round 7
// baseline (speedup 1.0000x reference)
#include <cuda_runtime.h>
#include <cstdint>

#define BB 8
#define TT 2048
#define DD 1024
#define NTOK (BB*TT)       // 16384
#define ROWF4 (DD/4)       // 256

// ---------------- scratch (no allocations allowed) ----------------
// layout: h(0), qkv(1..3), ab(4..5), dn(6)  -> 7 * 64MB = 448MB
__device__ float g_scratch[(size_t)7 * NTOK * DD];
__device__ float g_wt[(size_t)6 * DD * DD];   // wqkv(3) | wab(2) | wp(1)
__device__ float g_bias[5120];                 // bqkv(3072) | bab(2048)

// ---------------- helpers ----------------
__device__ __forceinline__ float sigmoidf_(float x) {
    return 1.0f / (1.0f + __expf(-x));
}
__device__ __forceinline__ float to_tf32(float x) {
    float r;
    asm("cvt.rna.tf32.f32 %0, %1;" : "=f"(r) : "f"(x));
    return r;
}
__device__ __forceinline__ uint32_t s2u(const void* p) {
    return (uint32_t)__cvta_generic_to_shared(p);
}

#define MMA_TF32(c, a, b)                                                       \
    asm volatile(                                                               \
        "mma.sync.aligned.m16n8k8.row.col.f32.tf32.tf32.f32 "                   \
        "{%0,%1,%2,%3},{%4,%5,%6,%7},{%8,%9},{%0,%1,%2,%3};\n"                  \
        : "+f"((c)[0]), "+f"((c)[1]), "+f"((c)[2]), "+f"((c)[3])                \
        : "r"((a)[0]), "r"((a)[1]), "r"((a)[2]), "r"((a)[3]),                   \
          "r"((b)[0]), "r"((b)[1]))

#define CP16(smem_addr, gptr)                                                   \
    asm volatile("cp.async.cg.shared.global [%0], [%1], 16;"                    \
                 :: "r"(smem_addr), "l"(gptr) : "memory")
#define CP_COMMIT() asm volatile("cp.async.commit_group;" ::: "memory")

// ---------------- prep: tf32-round weights into concat layouts + bias concat ----------------
__global__ void prep_kernel(const float* __restrict__ Wq, const float* __restrict__ Wk,
                            const float* __restrict__ Wv, const float* __restrict__ Wa,
                            const float* __restrict__ Wb, const float* __restrict__ Wp,
                            const float* __restrict__ bq, const float* __restrict__ bk,
                            const float* __restrict__ bv, const float* __restrict__ ba,
                            const float* __restrict__ bb) {
    const int blk = blockIdx.x;
    if (blk < 6144) {
        const int s = blk >> 10;
        const int idx = (blk & 1023) * 256 + threadIdx.x;
        const int k  = idx >> 8;
        const int n4 = idx & 255;
        const float* srcs[6] = {Wq, Wk, Wv, Wa, Wb, Wp};
        float4 v = ((const float4*)srcs[s])[idx];
        v = make_float4(to_tf32(v.x), to_tf32(v.y), to_tf32(v.z), to_tf32(v.w));
        float* dst;
        if (s < 3)       dst = g_wt + (size_t)k * 3072 + s * 1024;
        else if (s < 5)  dst = g_wt + (size_t)3 * DD * DD + (size_t)k * 2048 + (s-3)*1024;
        else             dst = g_wt + (size_t)5 * DD * DD + (size_t)k * 1024;
        ((float4*)dst)[n4] = v;
    } else {
        const int tid = threadIdx.x;
        for (int i = tid; i < 1024; i += 256) {
            g_bias[i]        = bq[i];
            g_bias[1024 + i] = bk[i];
            g_bias[2048 + i] = bv[i];
            g_bias[3072 + i] = ba[i];
            g_bias[4096 + i] = bb[i];
        }
    }
}

// ---------------- zc_rms: h = tf32(zc_rms(x)) ----------------
__global__ void zc_rms_kernel(const float4* __restrict__ x,
                              const float4* __restrict__ g,
                              float4* __restrict__ out) {
    __shared__ float red[16];
    const int row = blockIdx.x;
    const int tid = threadIdx.x;
    const size_t base = (size_t)row * ROWF4 + tid;

    float4 v = x[base];
    float s  = v.x + v.y + v.z + v.w;
    float s2 = v.x*v.x + v.y*v.y + v.z*v.z + v.w*v.w;
#pragma unroll
    for (int o = 16; o; o >>= 1) {
        s  += __shfl_xor_sync(0xffffffffu, s,  o);
        s2 += __shfl_xor_sync(0xffffffffu, s2, o);
    }
    const int w = tid >> 5, l = tid & 31;
    if (l == 0) { red[w] = s; red[8 + w] = s2; }
    __syncthreads();
    s = 0.f; s2 = 0.f;
#pragma unroll
    for (int i = 0; i < 8; i++) { s += red[i]; s2 += red[8 + i]; }

    const float mean = s * (1.0f / DD);
    const float var  = s2 * (1.0f / DD) - mean * mean;
    const float r    = rsqrtf(var + 1e-8f);

    float4 gv = g[tid];
    float4 o;
    o.x = to_tf32((v.x - mean) * r * gv.x);
    o.y = to_tf32((v.y - mean) * r * gv.y);
    o.z = to_tf32((v.z - mean) * r * gv.z);
    o.w = to_tf32((v.w - mean) * r * gv.w);
    out[base] = o;
}

// ---------------- fused conv3+sigmoid (q,k,v) + l2norm + delta + zc_rms ----------------
#define TCHUNK 8
__global__ void conv_delta_kernel(const float4* __restrict__ qkv,
                                  const float4* __restrict__ ab,
                                  const float* __restrict__ wq, const float* __restrict__ cbq,
                                  const float* __restrict__ wk, const float* __restrict__ cbk,
                                  const float* __restrict__ wv, const float* __restrict__ cbv,
                                  const float4* __restrict__ g2,
                                  float4* __restrict__ out) {
    __shared__ float redA[2][16];
    __shared__ float redB[2][16];
    const int row0 = blockIdx.x * TCHUNK;
    const int tid = threadIdx.x;
    const int t0 = row0 & (TT - 1);
    const int d0 = tid * 4;
    const int w = tid >> 5, l = tid & 31;

    float cw[3][12], cbr[3][4];
#pragma unroll
    for (int j = 0; j < 4; j++) {
#pragma unroll
        for (int c = 0; c < 3; c++) {
            cw[0][j * 3 + c] = wq[(d0 + j) * 3 + c];
            cw[1][j * 3 + c] = wk[(d0 + j) * 3 + c];
            cw[2][j * 3 + c] = wv[(d0 + j) * 3 + c];
        }
        cbr[0][j] = cbq[d0 + j];
        cbr[1][j] = cbk[d0 + j];
        cbr[2][j] = cbv[d0 + j];
    }
    const float4 g2v = g2[tid];

    const size_t qbase = (size_t)row0 * 768 + tid;
    const float4 Z = make_float4(0.f, 0.f, 0.f, 0.f);

    float4 qm, qc, km, kc, vm, vc;
    qc = qkv[qbase];
    kc = qkv[qbase + 256];
    vc = qkv[qbase + 512];
    if (t0 > 0) {
        qm = qkv[qbase - 768];
        km = qkv[qbase - 768 + 256];
        vm = qkv[qbase - 768 + 512];
    } else { qm = Z; km = Z; vm = Z; }

    for (int i = 0; i < TCHUNK; i++) {
        const int row = row0 + i;
        const int t = t0 + i;
        const size_t qb = qbase + (size_t)i * 768;
        float4 qp, kp, vp;
        if (t < TT - 1) {
            qp = qkv[qb + 768];
            kp = qkv[qb + 768 + 256];
            vp = qkv[qb + 768 + 512];
        } else { qp = Z; kp = Z; vp = Z; }

        const size_t abb = (size_t)row * 512 + tid;
        float4 av = ab[abb], bv = ab[abb + 256];

        float4 qv, kv, vv;
#define C1(st, j, m, c, p) sigmoidf_(fmaf(cw[st][j*3+0], (m), fmaf(cw[st][j*3+1], (c), fmaf(cw[st][j*3+2], (p), cbr[st][j]))))
        qv.x = C1(0, 0, qm.x, qc.x, qp.x); qv.y = C1(0, 1, qm.y, qc.y, qp.y);
        qv.z = C1(0, 2, qm.z, qc.z, qp.z); qv.w = C1(0, 3, qm.w, qc.w, qp.w);
        kv.x = C1(1, 0, km.x, kc.x, kp.x); kv.y = C1(1, 1, km.y, kc.y, kp.y);
        kv.z = C1(1, 2, km.z, kc.z, kp.z); kv.w = C1(1, 3, km.w, kc.w, kp.w);
        vv.x = C1(2, 0, vm.x, vc.x, vp.x); vv.y = C1(2, 1, vm.y, vc.y, vp.y);
        vv.z = C1(2, 2, vm.z, vc.z, vp.z); vv.w = C1(2, 3, vm.w, vc.w, vp.w);
#undef C1
        qm = qc; qc = qp; km = kc; kc = kp; vm = vc; vc = vp;

        const int par = i & 1;
        float sq = qv.x*qv.x + qv.y*qv.y + qv.z*qv.z + qv.w*qv.w;
        float sk = kv.x*kv.x + kv.y*kv.y + kv.z*kv.z + kv.w*kv.w;
#pragma unroll
        for (int o = 16; o; o >>= 1) {
            sq += __shfl_xor_sync(0xffffffffu, sq, o);
            sk += __shfl_xor_sync(0xffffffffu, sk, o);
        }
        if (l == 0) { redA[par][w] = sq; redA[par][8 + w] = sk; }
        __syncthreads();
        sq = 0.f; sk = 0.f;
#pragma unroll
        for (int j = 0; j < 8; j++) { sq += redA[par][j]; sk += redA[par][8 + j]; }

        const float rq = rsqrtf(sq + 1e-8f);
        const float rk = rsqrtf(sk + 1e-8f);

        float dd0 = fmaf(tanhf(av.x), (qv.x*rq)*(kv.x*rk)*vv.x, bv.x);
        float dd1 = fmaf(tanhf(av.y), (qv.y*rq)*(kv.y*rk)*vv.y, bv.y);
        float dd2 = fmaf(tanhf(av.z), (qv.z*rq)*(kv.z*rk)*vv.z, bv.z);
        float dd3 = fmaf(tanhf(av.w), (qv.w*rq)*(kv.w*rk)*vv.w, bv.w);

        float s  = dd0 + dd1 + dd2 + dd3;
        float s2 = dd0*dd0 + dd1*dd1 + dd2*dd2 + dd3*dd3;
#pragma unroll
        for (int o = 16; o; o >>= 1) {
            s  += __shfl_xor_sync(0xffffffffu, s,  o);
            s2 += __shfl_xor_sync(0xffffffffu, s2, o);
        }
        if (l == 0) { redB[par][w] = s; redB[par][8 + w] = s2; }
        __syncthreads();
        s = 0.f; s2 = 0.f;
#pragma unroll
        for (int j = 0; j < 8; j++) { s += redB[par][j]; s2 += redB[par][8 + j]; }

        const float mean = s * (1.0f / DD);
        const float var  = s2 * (1.0f / DD) - mean * mean;
        const float r    = rsqrtf(var + 1e-8f);

        float4 o;
        o.x = to_tf32((dd0 - mean) * r * g2v.x);
        o.y = to_tf32((dd1 - mean) * r * g2v.y);
        o.z = to_tf32((dd2 - mean) * r * g2v.z);
        o.w = to_tf32((dd3 - mean) * r * g2v.w);
        out[(size_t)row * ROWF4 + tid] = o;
    }
}

// ---------------- tf32 mma GEMM, 128x128 tile, 8 warps (32x64 each), 3-stage cp.async ----------------
// 16 warps/SM (2 CTA) -> 4 warps/SMSP for latency hiding.
// EPI==1: d = acc + bias; C = X + sigmoid(silu(d)) * d

#define AS_STRIDE 36      // floats; frag bank = 4g+tg (conflict-free)
#define BS_STRIDE 136     // floats; frag bank = 8tg+g (conflict-free)
#define AS_BYTES  (128 * AS_STRIDE * 4)          // 18432
#define BS_BYTES  (32 * BS_STRIDE * 4)           // 17408
#define STAGE_BYTES (AS_BYTES + BS_BYTES)        // 35840
#define NUM_STAGES 3
#define SMEM_GEMM (NUM_STAGES * STAGE_BYTES)     // 107520 (2 CTA/SM)

template <int EPI>
__global__ __launch_bounds__(256, 2)
void gemm_kernel(const float* __restrict__ A,
                 const float* __restrict__ W, const int ldw,
                 const float* __restrict__ bias,
                 const float* __restrict__ X,
                 float* __restrict__ C, const int ldc) {
    extern __shared__ __align__(16) char smem[];
    const int tid = threadIdx.x;
    const int m0 = blockIdx.y * 128;
    const int n0 = blockIdx.x * 128;
    const int warp = tid >> 5, lane = tid & 31;
    const int g = lane >> 2, tg = lane & 3;
    const int mBase = (warp & 3) * 32;    // 4 warps along M
    const int nBase = (warp >> 2) * 64;   // 2 warps along N

    const uint32_t smem_u = s2u(smem);
    const float* smem_f = (const float*)smem;

    // per-thread gmem load coords (256 threads)
    const int rowA = tid >> 3, k4A = tid & 7;    // A rows rowA + i*32, i=0..3
    const int rowB = tid >> 5, c4B = tid & 31;   // B rows rowB + i*8,  i=0..3
    const float* gA = A + (size_t)(m0 + rowA) * DD + k4A * 4;
    const float* gB = W + (size_t)rowB * ldw + n0 + c4B * 4;

    float acc[2][8][4];
#pragma unroll
    for (int mi = 0; mi < 2; mi++)
#pragma unroll
        for (int ni = 0; ni < 8; ni++)
#pragma unroll
            for (int i = 0; i < 4; i++) acc[mi][ni][i] = 0.f;

#define LOAD_CHUNK(k0, stage)                                                   \
    {                                                                           \
        const uint32_t sA = smem_u + (stage) * STAGE_BYTES;                     \
        const uint32_t sB = sA + AS_BYTES;                                      \
        _Pragma("unroll")                                                       \
        for (int i = 0; i < 4; i++)                                             \
            CP16(sA + (rowA + i * 32) * 144 + k4A * 16,                         \
                 gA + (size_t)(i * 32) * DD + (k0));                            \
        _Pragma("unroll")                                                       \
        for (int i = 0; i < 4; i++)                                             \
            CP16(sB + (rowB + i * 8) * 544 + c4B * 16,                          \
                 gB + (size_t)((k0) + i * 8) * ldw);                            \
    }

    LOAD_CHUNK(0, 0);  CP_COMMIT();
    LOAD_CHUNK(32, 1); CP_COMMIT();

    for (int kt = 0; kt < 32; ++kt) {
        if (kt < 31) asm volatile("cp.async.wait_group 1;" ::: "memory");
        else         asm volatile("cp.async.wait_group 0;" ::: "memory");
        __syncthreads();

        const int s = kt % 3;
        const float* As = smem_f + (s * STAGE_BYTES) / 4;
        const float* Bs = As + AS_BYTES / 4;

        const bool doPf = (kt + 2 < 32);
        const int pfk0 = (kt + 2) * 32;
        const int pfs = (kt + 2) % 3;
        const uint32_t pA = smem_u + pfs * STAGE_BYTES;
        const uint32_t pB = pA + AS_BYTES;

#pragma unroll
        for (int kk8 = 0; kk8 < 4; kk8++) {
            const int kk = kk8 * 8;
            // spread gmem prefetch: 1 A-f4 + 1 B-f4 per thread per kk step
            if (doPf) {
                CP16(pA + (rowA + kk8 * 32) * 144 + k4A * 16,
                     gA + (size_t)(kk8 * 32) * DD + pfk0);
                CP16(pB + (rowB + kk8 * 8) * 544 + c4B * 16,
                     gB + (size_t)(pfk0 + kk8 * 8) * ldw);
            }
            uint32_t af[2][4], bf[8][2];
#pragma unroll
            for (int mi = 0; mi < 2; mi++) {
                const int r0 = mBase + mi * 16 + g;
                af[mi][0] = __float_as_uint(As[r0 * AS_STRIDE + kk + tg]);
                af[mi][1] = __float_as_uint(As[(r0 + 8) * AS_STRIDE + kk + tg]);
                af[mi][2] = __float_as_uint(As[r0 * AS_STRIDE + kk + tg + 4]);
                af[mi][3] = __float_as_uint(As[(r0 + 8) * AS_STRIDE + kk + tg + 4]);
            }
#pragma unroll
            for (int ni = 0; ni < 8; ni++) {
                const int cn = nBase + ni * 8 + g;
                bf[ni][0] = __float_as_uint(Bs[(kk + tg) * BS_STRIDE + cn]);
                bf[ni][1] = __float_as_uint(Bs[(kk + tg + 4) * BS_STRIDE + cn]);
            }
#pragma unroll
            for (int mi = 0; mi < 2; mi++)
#pragma unroll
                for (int ni = 0; ni < 8; ni++)
                    MMA_TF32(acc[mi][ni], af[mi], bf[ni]);
        }
        if (doPf) CP_COMMIT();
    }
#undef LOAD_CHUNK

    // ---------------- epilogue ----------------
#pragma unroll
    for (int mi = 0; mi < 2; mi++) {
#pragma unroll
        for (int ni = 0; ni < 8; ni++) {
            const int r = m0 + mBase + mi * 16 + g;
            const int c = n0 + nBase + ni * 8 + 2 * tg;
            const float b0 = __ldg(bias + c);
            const float b1 = __ldg(bias + c + 1);
#pragma unroll
            for (int half = 0; half < 2; half++) {
                const int rr = r + half * 8;
                float da = acc[mi][ni][half * 2 + 0] + b0;
                float db = acc[mi][ni][half * 2 + 1] + b1;
                float oa, ob;
                if (EPI == 1) {
                    const float sa = da * sigmoidf_(da);   // silu
                    const float sb = db * sigmoidf_(db);
                    const float2 xv = *(const float2*)(X + (size_t)rr * DD + c);
                    oa = xv.x + sigmoidf_(sa) * da;
                    ob = xv.y + sigmoidf_(sb) * db;
                } else {
                    oa = da; ob = db;
                }
                *(float2*)(C + (size_t)rr * ldc + c) = make_float2(oa, ob);
            }
        }
    }
}

// ---------------- launch ----------------
extern "C" void kernel_launch(void* const* d_in, const int* in_sizes, int n_in,
                              void* d_out, int out_size) {
    const float* x   = (const float*)d_in[0];
    const float* g1  = (const float*)d_in[1];
    const float* Wq  = (const float*)d_in[2];
    const float* bq  = (const float*)d_in[3];
    const float* Wk  = (const float*)d_in[4];
    const float* bk  = (const float*)d_in[5];
    const float* Wv  = (const float*)d_in[6];
    const float* bv  = (const float*)d_in[7];
    const float* wqc = (const float*)d_in[8];
    const float* bqc = (const float*)d_in[9];
    const float* wkc = (const float*)d_in[10];
    const float* bkc = (const float*)d_in[11];
    const float* wvc = (const float*)d_in[12];
    const float* bvc = (const float*)d_in[13];
    const float* Wa  = (const float*)d_in[14];
    const float* ba  = (const float*)d_in[15];
    const float* Wb  = (const float*)d_in[16];
    const float* bb  = (const float*)d_in[17];
    const float* g2  = (const float*)d_in[18];
    const float* Wp  = (const float*)d_in[19];
    const float* bp  = (const float*)d_in[20];
    float* out = (float*)d_out;

    float* sc = nullptr;
    cudaGetSymbolAddress((void**)&sc, g_scratch);
    float* wt = nullptr;
    cudaGetSymbolAddress((void**)&wt, g_wt);
    float* bc = nullptr;
    cudaGetSymbolAddress((void**)&bc, g_bias);

    const size_t SZ = (size_t)NTOK * DD;
    float* h    = sc + 0 * SZ;
    float* qkv  = sc + 1 * SZ;   // [16384, 3072]
    float* abp  = sc + 4 * SZ;   // [16384, 2048]
    float* dn   = sc + 6 * SZ;

    const size_t WSZ = (size_t)DD * DD;
    float* Wqkv = wt + 0 * WSZ;  // [1024, 3072]
    float* Wab  = wt + 3 * WSZ;  // [1024, 2048]
    float* Wpr  = wt + 5 * WSZ;  // [1024, 1024]

    cudaFuncSetAttribute(gemm_kernel<0>, cudaFuncAttributeMaxDynamicSharedMemorySize, SMEM_GEMM);
    cudaFuncSetAttribute(gemm_kernel<1>, cudaFuncAttributeMaxDynamicSharedMemorySize, SMEM_GEMM);

    // [1] prep (weights + biases)
    prep_kernel<<<6145, 256>>>(Wq, Wk, Wv, Wa, Wb, Wp, bq, bk, bv, ba, bb);

    // [2] zc_rms
    zc_rms_kernel<<<NTOK, 256>>>((const float4*)x, (const float4*)g1, (float4*)h);

    // [3] qkv GEMM  (N = 3072)
    gemm_kernel<0><<<dim3(24, 128), 256, SMEM_GEMM>>>(h, Wqkv, 3072, bc, nullptr, qkv, 3072);
    // [4] ab GEMM   (N = 2048) — A = raw x (HW tf32 truncation of A operand)
    gemm_kernel<0><<<dim3(16, 128), 256, SMEM_GEMM>>>(x, Wab, 2048, bc + 3072, nullptr, abp, 2048);

    // [5] fused conv/delta/norm (rolling t-window)
    conv_delta_kernel<<<NTOK / TCHUNK, 256>>>((const float4*)qkv, (const float4*)abp,
                                              wqc, bqc, wkc, bkc, wvc, bvc,
                                              (const float4*)g2, (float4*)dn);

    // [6] final GEMM + residual epilogue
    gemm_kernel<1><<<dim3(8, 128), 256, SMEM_GEMM>>>(dn, Wpr, 1024, bp, x, out, 1024);
}

// round 8
// speedup vs baseline: 1.1000x; 1.1000x over previous
#include <cuda_runtime.h>
#include <cstdint>

#define BB 8
#define TT 2048
#define DD 1024
#define NTOK (BB*TT)       // 16384
#define ROWF4 (DD/4)       // 256

// ---------------- scratch (no allocations allowed) ----------------
// layout: h(0), qkv(1..3), ab(4..5), dn(6)  -> 7 * 64MB = 448MB
__device__ float g_scratch[(size_t)7 * NTOK * DD];
// transposed tf32 weights, [n][k] rows of 1024: qkv rows 0..3071 | ab rows 3072..5119 | p rows 5120..6143
__device__ float g_wt[(size_t)6 * DD * DD];
__device__ float g_bias[5120];                 // bqkv(3072) | bab(2048)

// ---------------- helpers ----------------
__device__ __forceinline__ float sigmoidf_(float x) {
    return 1.0f / (1.0f + __expf(-x));
}
__device__ __forceinline__ float to_tf32(float x) {
    float r;
    asm("cvt.rna.tf32.f32 %0, %1;" : "=f"(r) : "f"(x));
    return r;
}
__device__ __forceinline__ uint32_t s2u(const void* p) {
    return (uint32_t)__cvta_generic_to_shared(p);
}

#define MMA_TF32(c, a, b)                                                       \
    asm volatile(                                                               \
        "mma.sync.aligned.m16n8k8.row.col.f32.tf32.tf32.f32 "                   \
        "{%0,%1,%2,%3},{%4,%5,%6,%7},{%8,%9},{%0,%1,%2,%3};\n"                  \
        : "+f"((c)[0]), "+f"((c)[1]), "+f"((c)[2]), "+f"((c)[3])                \
        : "r"((a)[0]), "r"((a)[1]), "r"((a)[2]), "r"((a)[3]),                   \
          "r"((b)[0]), "r"((b)[1]))

#define LDSM4(r0, r1, r2, r3, addr)                                             \
    asm volatile("ldmatrix.sync.aligned.m8n8.x4.shared.b16 {%0,%1,%2,%3}, [%4];"\
        : "=r"(r0), "=r"(r1), "=r"(r2), "=r"(r3) : "r"(addr))

#define CP16(smem_addr, gptr)                                                   \
    asm volatile("cp.async.cg.shared.global [%0], [%1], 16;"                    \
                 :: "r"(smem_addr), "l"(gptr) : "memory")
#define CP_COMMIT() asm volatile("cp.async.commit_group;" ::: "memory")

// ---------------- prep: transpose + tf32-round weights; bias concat ----------------
// grid (32, 32, 7), block (32, 8). z = weight index; z == 6 -> bias concat (block (0,0) only).
__global__ void prep_kernel(const float* __restrict__ Wq, const float* __restrict__ Wk,
                            const float* __restrict__ Wv, const float* __restrict__ Wa,
                            const float* __restrict__ Wb, const float* __restrict__ Wp,
                            const float* __restrict__ bq, const float* __restrict__ bk,
                            const float* __restrict__ bv, const float* __restrict__ ba,
                            const float* __restrict__ bb) {
    const int s = blockIdx.z;
    if (s == 6) {
        if (blockIdx.x != 0 || blockIdx.y != 0) return;
        const int tid = threadIdx.y * 32 + threadIdx.x;
        for (int i = tid; i < 1024; i += 256) {
            g_bias[i]        = bq[i];
            g_bias[1024 + i] = bk[i];
            g_bias[2048 + i] = bv[i];
            g_bias[3072 + i] = ba[i];
            g_bias[4096 + i] = bb[i];
        }
        return;
    }
    const float* srcs[6] = {Wq, Wk, Wv, Wa, Wb, Wp};
    const float* S = srcs[s];
    __shared__ float t[32][33];
    const int bx = blockIdx.x * 32, by = blockIdx.y * 32;
    const int tx = threadIdx.x, ty = threadIdx.y;
    // read S[k = by+row][n = bx+tx]
#pragma unroll
    for (int i = 0; i < 4; i++)
        t[ty + 8 * i][tx] = S[(size_t)(by + ty + 8 * i) * DD + bx + tx];
    __syncthreads();
    // write Wt[row n = s*1024 + bx + r][k = by + tx]
    float* D = g_wt + (size_t)s * DD * DD;
#pragma unroll
    for (int i = 0; i < 4; i++)
        D[(size_t)(bx + ty + 8 * i) * DD + by + tx] = to_tf32(t[tx][ty + 8 * i]);
}

// ---------------- zc_rms: h = tf32(zc_rms(x)) ----------------
__global__ void zc_rms_kernel(const float4* __restrict__ x,
                              const float4* __restrict__ g,
                              float4* __restrict__ out) {
    __shared__ float red[16];
    const int row = blockIdx.x;
    const int tid = threadIdx.x;
    const size_t base = (size_t)row * ROWF4 + tid;

    float4 v = x[base];
    float s  = v.x + v.y + v.z + v.w;
    float s2 = v.x*v.x + v.y*v.y + v.z*v.z + v.w*v.w;
#pragma unroll
    for (int o = 16; o; o >>= 1) {
        s  += __shfl_xor_sync(0xffffffffu, s,  o);
        s2 += __shfl_xor_sync(0xffffffffu, s2, o);
    }
    const int w = tid >> 5, l = tid & 31;
    if (l == 0) { red[w] = s; red[8 + w] = s2; }
    __syncthreads();
    s = 0.f; s2 = 0.f;
#pragma unroll
    for (int i = 0; i < 8; i++) { s += red[i]; s2 += red[8 + i]; }

    const float mean = s * (1.0f / DD);
    const float var  = s2 * (1.0f / DD) - mean * mean;
    const float r    = rsqrtf(var + 1e-8f);

    float4 gv = g[tid];
    float4 o;
    o.x = to_tf32((v.x - mean) * r * gv.x);
    o.y = to_tf32((v.y - mean) * r * gv.y);
    o.z = to_tf32((v.z - mean) * r * gv.z);
    o.w = to_tf32((v.w - mean) * r * gv.w);
    out[base] = o;
}

// ---------------- fused conv3+sigmoid (q,k,v) + l2norm + delta + zc_rms ----------------
#define TCHUNK 8
__global__ void conv_delta_kernel(const float4* __restrict__ qkv,
                                  const float4* __restrict__ ab,
                                  const float* __restrict__ wq, const float* __restrict__ cbq,
                                  const float* __restrict__ wk, const float* __restrict__ cbk,
                                  const float* __restrict__ wv, const float* __restrict__ cbv,
                                  const float4* __restrict__ g2,
                                  float4* __restrict__ out) {
    __shared__ float redA[2][16];
    __shared__ float redB[2][16];
    const int row0 = blockIdx.x * TCHUNK;
    const int tid = threadIdx.x;
    const int t0 = row0 & (TT - 1);
    const int d0 = tid * 4;
    const int w = tid >> 5, l = tid & 31;

    float cw[3][12], cbr[3][4];
#pragma unroll
    for (int j = 0; j < 4; j++) {
#pragma unroll
        for (int c = 0; c < 3; c++) {
            cw[0][j * 3 + c] = wq[(d0 + j) * 3 + c];
            cw[1][j * 3 + c] = wk[(d0 + j) * 3 + c];
            cw[2][j * 3 + c] = wv[(d0 + j) * 3 + c];
        }
        cbr[0][j] = cbq[d0 + j];
        cbr[1][j] = cbk[d0 + j];
        cbr[2][j] = cbv[d0 + j];
    }
    const float4 g2v = g2[tid];

    const size_t qbase = (size_t)row0 * 768 + tid;
    const float4 Z = make_float4(0.f, 0.f, 0.f, 0.f);

    float4 qm, qc, km, kc, vm, vc;
    qc = qkv[qbase];
    kc = qkv[qbase + 256];
    vc = qkv[qbase + 512];
    if (t0 > 0) {
        qm = qkv[qbase - 768];
        km = qkv[qbase - 768 + 256];
        vm = qkv[qbase - 768 + 512];
    } else { qm = Z; km = Z; vm = Z; }

    for (int i = 0; i < TCHUNK; i++) {
        const int row = row0 + i;
        const int t = t0 + i;
        const size_t qb = qbase + (size_t)i * 768;
        float4 qp, kp, vp;
        if (t < TT - 1) {
            qp = qkv[qb + 768];
            kp = qkv[qb + 768 + 256];
            vp = qkv[qb + 768 + 512];
        } else { qp = Z; kp = Z; vp = Z; }

        const size_t abb = (size_t)row * 512 + tid;
        float4 av = ab[abb], bv = ab[abb + 256];

        float4 qv, kv, vv;
#define C1(st, j, m, c, p) sigmoidf_(fmaf(cw[st][j*3+0], (m), fmaf(cw[st][j*3+1], (c), fmaf(cw[st][j*3+2], (p), cbr[st][j]))))
        qv.x = C1(0, 0, qm.x, qc.x, qp.x); qv.y = C1(0, 1, qm.y, qc.y, qp.y);
        qv.z = C1(0, 2, qm.z, qc.z, qp.z); qv.w = C1(0, 3, qm.w, qc.w, qp.w);
        kv.x = C1(1, 0, km.x, kc.x, kp.x); kv.y = C1(1, 1, km.y, kc.y, kp.y);
        kv.z = C1(1, 2, km.z, kc.z, kp.z); kv.w = C1(1, 3, km.w, kc.w, kp.w);
        vv.x = C1(2, 0, vm.x, vc.x, vp.x); vv.y = C1(2, 1, vm.y, vc.y, vp.y);
        vv.z = C1(2, 2, vm.z, vc.z, vp.z); vv.w = C1(2, 3, vm.w, vc.w, vp.w);
#undef C1
        qm = qc; qc = qp; km = kc; kc = kp; vm = vc; vc = vp;

        const int par = i & 1;
        float sq = qv.x*qv.x + qv.y*qv.y + qv.z*qv.z + qv.w*qv.w;
        float sk = kv.x*kv.x + kv.y*kv.y + kv.z*kv.z + kv.w*kv.w;
#pragma unroll
        for (int o = 16; o; o >>= 1) {
            sq += __shfl_xor_sync(0xffffffffu, sq, o);
            sk += __shfl_xor_sync(0xffffffffu, sk, o);
        }
        if (l == 0) { redA[par][w] = sq; redA[par][8 + w] = sk; }
        __syncthreads();
        sq = 0.f; sk = 0.f;
#pragma unroll
        for (int j = 0; j < 8; j++) { sq += redA[par][j]; sk += redA[par][8 + j]; }

        const float rq = rsqrtf(sq + 1e-8f);
        const float rk = rsqrtf(sk + 1e-8f);

        float dd0 = fmaf(tanhf(av.x), (qv.x*rq)*(kv.x*rk)*vv.x, bv.x);
        float dd1 = fmaf(tanhf(av.y), (qv.y*rq)*(kv.y*rk)*vv.y, bv.y);
        float dd2 = fmaf(tanhf(av.z), (qv.z*rq)*(kv.z*rk)*vv.z, bv.z);
        float dd3 = fmaf(tanhf(av.w), (qv.w*rq)*(kv.w*rk)*vv.w, bv.w);

        float s  = dd0 + dd1 + dd2 + dd3;
        float s2 = dd0*dd0 + dd1*dd1 + dd2*dd2 + dd3*dd3;
#pragma unroll
        for (int o = 16; o; o >>= 1) {
            s  += __shfl_xor_sync(0xffffffffu, s,  o);
            s2 += __shfl_xor_sync(0xffffffffu, s2, o);
        }
        if (l == 0) { redB[par][w] = s; redB[par][8 + w] = s2; }
        __syncthreads();
        s = 0.f; s2 = 0.f;
#pragma unroll
        for (int j = 0; j < 8; j++) { s += redB[par][j]; s2 += redB[par][8 + j]; }

        const float mean = s * (1.0f / DD);
        const float var  = s2 * (1.0f / DD) - mean * mean;
        const float r    = rsqrtf(var + 1e-8f);

        float4 o;
        o.x = to_tf32((dd0 - mean) * r * g2v.x);
        o.y = to_tf32((dd1 - mean) * r * g2v.y);
        o.z = to_tf32((dd2 - mean) * r * g2v.z);
        o.w = to_tf32((dd3 - mean) * r * g2v.w);
        out[(size_t)row * ROWF4 + tid] = o;
    }
}

// ---------------- tf32 mma GEMM via LDSM, 128x128 tile, 4 warps (64x64 each) ----------------
// A [16384,1024] row-major (tf32); Wt [n][k] rows of 1024 (tf32). 3-stage cp.async.
// Fragments loaded with ldmatrix.x4 (U32x4 LDSM): 8 LDSM + 32 MMA per warp per kk-step.
// EPI==1: d = acc + bias; C = X + sigmoid(silu(d)) * d

#define TPITCH   144                             // bytes per 32-float row (36 floats)
#define AS_BYTES (128 * TPITCH)                  // 18432
#define BS_BYTES (128 * TPITCH)                  // 18432
#define STAGE_BYTES (AS_BYTES + BS_BYTES)        // 36864
#define NUM_STAGES 3
#define SMEM_GEMM (NUM_STAGES * STAGE_BYTES)     // 110592 (2 CTA/SM)

template <int EPI>
__global__ __launch_bounds__(128, 2)
void gemm_kernel(const float* __restrict__ A,
                 const float* __restrict__ Wt,   // [n][k] rows, pitch 1024
                 const float* __restrict__ bias,
                 const float* __restrict__ X,
                 float* __restrict__ C, const int ldc) {
    extern __shared__ __align__(16) char smem[];
    const int tid = threadIdx.x;
    const int m0 = blockIdx.y * 128;
    const int n0 = blockIdx.x * 128;
    const int warp = tid >> 5, lane = tid & 31;
    const int g = lane >> 2, tg = lane & 3;
    const int mBase = (warp >> 1) * 64;
    const int nBase = (warp & 1) * 64;

    const uint32_t smem_u = s2u(smem);

    // gmem load coords: both tiles are 128 rows x 32 floats (8 f4/row)
    const int rowL = tid >> 3, k4L = tid & 7;    // rows rowL + i*16, i = 0..7
    const float* gA = A  + (size_t)(m0 + rowL) * DD + k4L * 4;
    const float* gB = Wt + (size_t)(n0 + rowL) * DD + k4L * 4;

    // LDSM per-lane offsets (bytes within tile)
    const int q = lane >> 3, e = lane & 7;
    // A: mat0 rows+0 k0-3, mat1 rows+8 k0-3, mat2 rows+0 k4-7, mat3 rows+8 k4-7
    uint32_t aoff[4], boff[4];
#pragma unroll
    for (int mi = 0; mi < 4; mi++)
        aoff[mi] = (uint32_t)((mBase + mi * 16 + e + ((q & 1) << 3)) * TPITCH + ((q >> 1) << 4));
    // B: mat0 n+0 k0-3, mat1 n+0 k4-7, mat2 n+8 k0-3, mat3 n+8 k4-7  (pair p covers ni=2p,2p+1)
#pragma unroll
    for (int p = 0; p < 4; p++)
        boff[p] = (uint32_t)((nBase + p * 16 + ((q >> 1) << 3) + e) * TPITCH + ((q & 1) << 4));

    float acc[4][8][4];
#pragma unroll
    for (int mi = 0; mi < 4; mi++)
#pragma unroll
        for (int ni = 0; ni < 8; ni++)
#pragma unroll
            for (int i = 0; i < 4; i++) acc[mi][ni][i] = 0.f;

#define LOAD_CHUNK(k0, stage)                                                   \
    {                                                                           \
        const uint32_t sA = smem_u + (stage) * STAGE_BYTES;                     \
        const uint32_t sB = sA + AS_BYTES;                                      \
        _Pragma("unroll")                                                       \
        for (int i = 0; i < 8; i++)                                             \
            CP16(sA + (rowL + i * 16) * TPITCH + k4L * 16,                      \
                 gA + (size_t)(i * 16) * DD + (k0));                            \
        _Pragma("unroll")                                                       \
        for (int i = 0; i < 8; i++)                                             \
            CP16(sB + (rowL + i * 16) * TPITCH + k4L * 16,                      \
                 gB + (size_t)(i * 16) * DD + (k0));                            \
    }

    LOAD_CHUNK(0, 0);  CP_COMMIT();
    LOAD_CHUNK(32, 1); CP_COMMIT();

    for (int kt = 0; kt < 32; ++kt) {
        if (kt < 31) asm volatile("cp.async.wait_group 1;" ::: "memory");
        else         asm volatile("cp.async.wait_group 0;" ::: "memory");
        __syncthreads();

        const int s = kt % 3;
        const uint32_t sA = smem_u + s * STAGE_BYTES;
        const uint32_t sB = sA + AS_BYTES;

        const bool doPf = (kt + 2 < 32);
        const int pfk0 = (kt + 2) * 32;
        const int pfs = (kt + 2) % 3;
        const uint32_t pA = smem_u + pfs * STAGE_BYTES;
        const uint32_t pB = pA + AS_BYTES;

#pragma unroll
        for (int kk8 = 0; kk8 < 4; kk8++) {
            const uint32_t kb = kk8 * 32;   // kk * 4 bytes
            // spread gmem prefetch: 2 A-f4 + 2 B-f4 per thread per kk step
            if (doPf) {
#pragma unroll
                for (int j = 0; j < 2; j++) {
                    const int i = kk8 * 2 + j;
                    CP16(pA + (rowL + i * 16) * TPITCH + k4L * 16,
                         gA + (size_t)(i * 16) * DD + pfk0);
                    CP16(pB + (rowL + i * 16) * TPITCH + k4L * 16,
                         gB + (size_t)(i * 16) * DD + pfk0);
                }
            }
            uint32_t af[4][4], bf[8][2];
#pragma unroll
            for (int mi = 0; mi < 4; mi++)
                LDSM4(af[mi][0], af[mi][1], af[mi][2], af[mi][3], sA + aoff[mi] + kb);
#pragma unroll
            for (int p = 0; p < 4; p++)
                LDSM4(bf[2 * p][0], bf[2 * p][1], bf[2 * p + 1][0], bf[2 * p + 1][1],
                      sB + boff[p] + kb);
#pragma unroll
            for (int mi = 0; mi < 4; mi++)
#pragma unroll
                for (int ni = 0; ni < 8; ni++)
                    MMA_TF32(acc[mi][ni], af[mi], bf[ni]);
        }
        if (doPf) CP_COMMIT();
    }
#undef LOAD_CHUNK

    // ---------------- epilogue ----------------
#pragma unroll
    for (int mi = 0; mi < 4; mi++) {
#pragma unroll
        for (int ni = 0; ni < 8; ni++) {
            const int r = m0 + mBase + mi * 16 + g;
            const int c = n0 + nBase + ni * 8 + 2 * tg;
            const float b0 = __ldg(bias + c);
            const float b1 = __ldg(bias + c + 1);
#pragma unroll
            for (int half = 0; half < 2; half++) {
                const int rr = r + half * 8;
                float da = acc[mi][ni][half * 2 + 0] + b0;
                float db = acc[mi][ni][half * 2 + 1] + b1;
                float oa, ob;
                if (EPI == 1) {
                    const float sa = da * sigmoidf_(da);   // silu
                    const float sb = db * sigmoidf_(db);
                    const float2 xv = *(const float2*)(X + (size_t)rr * DD + c);
                    oa = xv.x + sigmoidf_(sa) * da;
                    ob = xv.y + sigmoidf_(sb) * db;
                } else {
                    oa = da; ob = db;
                }
                *(float2*)(C + (size_t)rr * ldc + c) = make_float2(oa, ob);
            }
        }
    }
}

// ---------------- launch ----------------
extern "C" void kernel_launch(void* const* d_in, const int* in_sizes, int n_in,
                              void* d_out, int out_size) {
    const float* x   = (const float*)d_in[0];
    const float* g1  = (const float*)d_in[1];
    const float* Wq  = (const float*)d_in[2];
    const float* bq  = (const float*)d_in[3];
    const float* Wk  = (const float*)d_in[4];
    const float* bk  = (const float*)d_in[5];
    const float* Wv  = (const float*)d_in[6];
    const float* bv  = (const float*)d_in[7];
    const float* wqc = (const float*)d_in[8];
    const float* bqc = (const float*)d_in[9];
    const float* wkc = (const float*)d_in[10];
    const float* bkc = (const float*)d_in[11];
    const float* wvc = (const float*)d_in[12];
    const float* bvc = (const float*)d_in[13];
    const float* Wa  = (const float*)d_in[14];
    const float* ba  = (const float*)d_in[15];
    const float* Wb  = (const float*)d_in[16];
    const float* bb  = (const float*)d_in[17];
    const float* g2  = (const float*)d_in[18];
    const float* Wp  = (const float*)d_in[19];
    const float* bp  = (const float*)d_in[20];
    float* out = (float*)d_out;

    float* sc = nullptr;
    cudaGetSymbolAddress((void**)&sc, g_scratch);
    float* wt = nullptr;
    cudaGetSymbolAddress((void**)&wt, g_wt);
    float* bc = nullptr;
    cudaGetSymbolAddress((void**)&bc, g_bias);

    const size_t SZ = (size_t)NTOK * DD;
    float* h    = sc + 0 * SZ;
    float* qkv  = sc + 1 * SZ;   // [16384, 3072]
    float* abp  = sc + 4 * SZ;   // [16384, 2048]
    float* dn   = sc + 6 * SZ;

    const size_t WSZ = (size_t)DD * DD;
    float* Wqkv_t = wt + 0 * WSZ;  // rows 0..3071
    float* Wab_t  = wt + 3 * WSZ;  // rows 0..2047
    float* Wp_t   = wt + 5 * WSZ;  // rows 0..1023

    cudaFuncSetAttribute(gemm_kernel<0>, cudaFuncAttributeMaxDynamicSharedMemorySize, SMEM_GEMM);
    cudaFuncSetAttribute(gemm_kernel<1>, cudaFuncAttributeMaxDynamicSharedMemorySize, SMEM_GEMM);

    // [1] prep (weight transpose + rna, bias concat)
    prep_kernel<<<dim3(32, 32, 7), dim3(32, 8)>>>(Wq, Wk, Wv, Wa, Wb, Wp,
                                                  bq, bk, bv, ba, bb);

    // [2] zc_rms
    zc_rms_kernel<<<NTOK, 256>>>((const float4*)x, (const float4*)g1, (float4*)h);

    // [3] qkv GEMM  (N = 3072)
    gemm_kernel<0><<<dim3(24, 128), 128, SMEM_GEMM>>>(h, Wqkv_t, bc, nullptr, qkv, 3072);
    // [4] ab GEMM   (N = 2048) — A = raw x (HW tf32 truncation of A operand)
    gemm_kernel<0><<<dim3(16, 128), 128, SMEM_GEMM>>>(x, Wab_t, bc + 3072, nullptr, abp, 2048);

    // [5] fused conv/delta/norm (rolling t-window)
    conv_delta_kernel<<<NTOK / TCHUNK, 256>>>((const float4*)qkv, (const float4*)abp,
                                              wqc, bqc, wkc, bkc, wvc, bvc,
                                              (const float4*)g2, (float4*)dn);

    // [6] final GEMM + residual epilogue
    gemm_kernel<1><<<dim3(8, 128), 128, SMEM_GEMM>>>(dn, Wp_t, bp, x, out, 1024);
}

// round 10
// speedup vs baseline: 1.1117x; 1.0106x over previous
#include <cuda_runtime.h>
#include <cstdint>

#define BB 8
#define TT 2048
#define DD 1024
#define NTOK (BB*TT)       // 16384
#define ROWF4 (DD/4)       // 256

// ---------------- scratch (no allocations allowed) ----------------
// layout: h(0), qkv(1..3), ab(4..5), dn(6)  -> 7 * 64MB = 448MB
__device__ float g_scratch[(size_t)7 * NTOK * DD];
// transposed tf32 weights, [n][k] rows of 1024: qkv rows 0..3071 | ab rows 3072..5119 | p rows 5120..6143
__device__ float g_wt[(size_t)6 * DD * DD];
__device__ float g_bias[5120];                 // bqkv(3072) | bab(2048)

// ---------------- helpers ----------------
__device__ __forceinline__ float sigmoidf_(float x) {
    return 1.0f / (1.0f + __expf(-x));
}
__device__ __forceinline__ float to_tf32(float x) {
    float r;
    asm("cvt.rna.tf32.f32 %0, %1;" : "=f"(r) : "f"(x));
    return r;
}
__device__ __forceinline__ uint32_t s2u(const void* p) {
    return (uint32_t)__cvta_generic_to_shared(p);
}

#define MMA_TF32(c, a, b)                                                       \
    asm volatile(                                                               \
        "mma.sync.aligned.m16n8k8.row.col.f32.tf32.tf32.f32 "                   \
        "{%0,%1,%2,%3},{%4,%5,%6,%7},{%8,%9},{%0,%1,%2,%3};\n"                  \
        : "+f"((c)[0]), "+f"((c)[1]), "+f"((c)[2]), "+f"((c)[3])                \
        : "r"((a)[0]), "r"((a)[1]), "r"((a)[2]), "r"((a)[3]),                   \
          "r"((b)[0]), "r"((b)[1]))

#define LDSM4(r0, r1, r2, r3, addr)                                             \
    asm volatile("ldmatrix.sync.aligned.m8n8.x4.shared.b16 {%0,%1,%2,%3}, [%4];"\
        : "=r"(r0), "=r"(r1), "=r"(r2), "=r"(r3) : "r"(addr))

#define CP16(smem_addr, gptr)                                                   \
    asm volatile("cp.async.cg.shared.global [%0], [%1], 16;"                    \
                 :: "r"(smem_addr), "l"(gptr) : "memory")
#define CP_COMMIT() asm volatile("cp.async.commit_group;" ::: "memory")

// ---------------- prep: transpose + tf32-round weights; bias concat ----------------
__global__ void prep_kernel(const float* __restrict__ Wq, const float* __restrict__ Wk,
                            const float* __restrict__ Wv, const float* __restrict__ Wa,
                            const float* __restrict__ Wb, const float* __restrict__ Wp,
                            const float* __restrict__ bq, const float* __restrict__ bk,
                            const float* __restrict__ bv, const float* __restrict__ ba,
                            const float* __restrict__ bb) {
    const int s = blockIdx.z;
    if (s == 6) {
        if (blockIdx.x != 0 || blockIdx.y != 0) return;
        const int tid = threadIdx.y * 32 + threadIdx.x;
        for (int i = tid; i < 1024; i += 256) {
            g_bias[i]        = bq[i];
            g_bias[1024 + i] = bk[i];
            g_bias[2048 + i] = bv[i];
            g_bias[3072 + i] = ba[i];
            g_bias[4096 + i] = bb[i];
        }
        return;
    }
    const float* srcs[6] = {Wq, Wk, Wv, Wa, Wb, Wp};
    const float* S = srcs[s];
    __shared__ float t[32][33];
    const int bx = blockIdx.x * 32, by = blockIdx.y * 32;
    const int tx = threadIdx.x, ty = threadIdx.y;
#pragma unroll
    for (int i = 0; i < 4; i++)
        t[ty + 8 * i][tx] = S[(size_t)(by + ty + 8 * i) * DD + bx + tx];
    __syncthreads();
    float* D = g_wt + (size_t)s * DD * DD;
#pragma unroll
    for (int i = 0; i < 4; i++)
        D[(size_t)(bx + ty + 8 * i) * DD + by + tx] = to_tf32(t[tx][ty + 8 * i]);
}

// ---------------- zc_rms: h = tf32(zc_rms(x)) ----------------
__global__ void zc_rms_kernel(const float4* __restrict__ x,
                              const float4* __restrict__ g,
                              float4* __restrict__ out) {
    __shared__ float red[16];
    const int row = blockIdx.x;
    const int tid = threadIdx.x;
    const size_t base = (size_t)row * ROWF4 + tid;

    float4 v = x[base];
    float s  = v.x + v.y + v.z + v.w;
    float s2 = v.x*v.x + v.y*v.y + v.z*v.z + v.w*v.w;
#pragma unroll
    for (int o = 16; o; o >>= 1) {
        s  += __shfl_xor_sync(0xffffffffu, s,  o);
        s2 += __shfl_xor_sync(0xffffffffu, s2, o);
    }
    const int w = tid >> 5, l = tid & 31;
    if (l == 0) { red[w] = s; red[8 + w] = s2; }
    __syncthreads();
    s = 0.f; s2 = 0.f;
#pragma unroll
    for (int i = 0; i < 8; i++) { s += red[i]; s2 += red[8 + i]; }

    const float mean = s * (1.0f / DD);
    const float var  = s2 * (1.0f / DD) - mean * mean;
    const float r    = rsqrtf(var + 1e-8f);

    float4 gv = g[tid];
    float4 o;
    o.x = to_tf32((v.x - mean) * r * gv.x);
    o.y = to_tf32((v.y - mean) * r * gv.y);
    o.z = to_tf32((v.z - mean) * r * gv.z);
    o.w = to_tf32((v.w - mean) * r * gv.w);
    out[base] = o;
}

// ---------------- fused conv3+sigmoid (q,k,v) + l2norm + delta + zc_rms ----------------
#define TCHUNK 8
__global__ void conv_delta_kernel(const float4* __restrict__ qkv,
                                  const float4* __restrict__ ab,
                                  const float* __restrict__ wq, const float* __restrict__ cbq,
                                  const float* __restrict__ wk, const float* __restrict__ cbk,
                                  const float* __restrict__ wv, const float* __restrict__ cbv,
                                  const float4* __restrict__ g2,
                                  float4* __restrict__ out) {
    __shared__ float redA[2][16];
    __shared__ float redB[2][16];
    const int row0 = blockIdx.x * TCHUNK;
    const int tid = threadIdx.x;
    const int t0 = row0 & (TT - 1);
    const int d0 = tid * 4;
    const int w = tid >> 5, l = tid & 31;

    float cw[3][12], cbr[3][4];
#pragma unroll
    for (int j = 0; j < 4; j++) {
#pragma unroll
        for (int c = 0; c < 3; c++) {
            cw[0][j * 3 + c] = wq[(d0 + j) * 3 + c];
            cw[1][j * 3 + c] = wk[(d0 + j) * 3 + c];
            cw[2][j * 3 + c] = wv[(d0 + j) * 3 + c];
        }
        cbr[0][j] = cbq[d0 + j];
        cbr[1][j] = cbk[d0 + j];
        cbr[2][j] = cbv[d0 + j];
    }
    const float4 g2v = g2[tid];

    const size_t qbase = (size_t)row0 * 768 + tid;
    const float4 Z = make_float4(0.f, 0.f, 0.f, 0.f);

    float4 qm, qc, km, kc, vm, vc;
    qc = qkv[qbase];
    kc = qkv[qbase + 256];
    vc = qkv[qbase + 512];
    if (t0 > 0) {
        qm = qkv[qbase - 768];
        km = qkv[qbase - 768 + 256];
        vm = qkv[qbase - 768 + 512];
    } else { qm = Z; km = Z; vm = Z; }

    for (int i = 0; i < TCHUNK; i++) {
        const int row = row0 + i;
        const int t = t0 + i;
        const size_t qb = qbase + (size_t)i * 768;
        float4 qp, kp, vp;
        if (t < TT - 1) {
            qp = qkv[qb + 768];
            kp = qkv[qb + 768 + 256];
            vp = qkv[qb + 768 + 512];
        } else { qp = Z; kp = Z; vp = Z; }

        const size_t abb = (size_t)row * 512 + tid;
        float4 av = ab[abb], bv = ab[abb + 256];

        float4 qv, kv, vv;
#define C1(st, j, m, c, p) sigmoidf_(fmaf(cw[st][j*3+0], (m), fmaf(cw[st][j*3+1], (c), fmaf(cw[st][j*3+2], (p), cbr[st][j]))))
        qv.x = C1(0, 0, qm.x, qc.x, qp.x); qv.y = C1(0, 1, qm.y, qc.y, qp.y);
        qv.z = C1(0, 2, qm.z, qc.z, qp.z); qv.w = C1(0, 3, qm.w, qc.w, qp.w);
        kv.x = C1(1, 0, km.x, kc.x, kp.x); kv.y = C1(1, 1, km.y, kc.y, kp.y);
        kv.z = C1(1, 2, km.z, kc.z, kp.z); kv.w = C1(1, 3, km.w, kc.w, kp.w);
        vv.x = C1(2, 0, vm.x, vc.x, vp.x); vv.y = C1(2, 1, vm.y, vc.y, vp.y);
        vv.z = C1(2, 2, vm.z, vc.z, vp.z); vv.w = C1(2, 3, vm.w, vc.w, vp.w);
#undef C1
        qm = qc; qc = qp; km = kc; kc = kp; vm = vc; vc = vp;

        const int par = i & 1;
        float sq = qv.x*qv.x + qv.y*qv.y + qv.z*qv.z + qv.w*qv.w;
        float sk = kv.x*kv.x + kv.y*kv.y + kv.z*kv.z + kv.w*kv.w;
#pragma unroll
        for (int o = 16; o; o >>= 1) {
            sq += __shfl_xor_sync(0xffffffffu, sq, o);
            sk += __shfl_xor_sync(0xffffffffu, sk, o);
        }
        if (l == 0) { redA[par][w] = sq; redA[par][8 + w] = sk; }
        __syncthreads();
        sq = 0.f; sk = 0.f;
#pragma unroll
        for (int j = 0; j < 8; j++) { sq += redA[par][j]; sk += redA[par][8 + j]; }

        const float rq = rsqrtf(sq + 1e-8f);
        const float rk = rsqrtf(sk + 1e-8f);

        float dd0 = fmaf(tanhf(av.x), (qv.x*rq)*(kv.x*rk)*vv.x, bv.x);
        float dd1 = fmaf(tanhf(av.y), (qv.y*rq)*(kv.y*rk)*vv.y, bv.y);
        float dd2 = fmaf(tanhf(av.z), (qv.z*rq)*(kv.z*rk)*vv.z, bv.z);
        float dd3 = fmaf(tanhf(av.w), (qv.w*rq)*(kv.w*rk)*vv.w, bv.w);

        float s  = dd0 + dd1 + dd2 + dd3;
        float s2 = dd0*dd0 + dd1*dd1 + dd2*dd2 + dd3*dd3;
#pragma unroll
        for (int o = 16; o; o >>= 1) {
            s  += __shfl_xor_sync(0xffffffffu, s,  o);
            s2 += __shfl_xor_sync(0xffffffffu, s2, o);
        }
        if (l == 0) { redB[par][w] = s; redB[par][8 + w] = s2; }
        __syncthreads();
        s = 0.f; s2 = 0.f;
#pragma unroll
        for (int j = 0; j < 8; j++) { s += redB[par][j]; s2 += redB[par][8 + j]; }

        const float mean = s * (1.0f / DD);
        const float var  = s2 * (1.0f / DD) - mean * mean;
        const float r    = rsqrtf(var + 1e-8f);

        float4 o;
        o.x = to_tf32((dd0 - mean) * r * g2v.x);
        o.y = to_tf32((dd1 - mean) * r * g2v.y);
        o.z = to_tf32((dd2 - mean) * r * g2v.z);
        o.w = to_tf32((dd3 - mean) * r * g2v.w);
        out[(size_t)row * ROWF4 + tid] = o;
    }
}

// ---------------- tf32 mma GEMM via LDSM, 128x128 tile, 4 warps (64x64 each) ----------------
// 3-stage cp.async + cross-kk-step LDSM fragment double-buffering.
// EPI==1: d = acc + bias; C = X + sigmoid(silu(d)) * d

#define TPITCH   144                             // bytes per 32-float row (36 floats)
#define AS_BYTES (128 * TPITCH)                  // 18432
#define BS_BYTES (128 * TPITCH)                  // 18432
#define STAGE_BYTES (AS_BYTES + BS_BYTES)        // 36864
#define NUM_STAGES 3
#define SMEM_GEMM (NUM_STAGES * STAGE_BYTES)     // 110592 (2 CTA/SM)

template <int EPI>
__global__ __launch_bounds__(128, 2)
void gemm_kernel(const float* __restrict__ A,
                 const float* __restrict__ Wt,   // [n][k] rows, pitch 1024
                 const float* __restrict__ bias,
                 const float* __restrict__ X,
                 float* __restrict__ C, const int ldc) {
    extern __shared__ __align__(16) char smem[];
    const int tid = threadIdx.x;
    const int m0 = blockIdx.y * 128;
    const int n0 = blockIdx.x * 128;
    const int warp = tid >> 5, lane = tid & 31;
    const int g = lane >> 2, tg = lane & 3;
    const int mBase = (warp >> 1) * 64;
    const int nBase = (warp & 1) * 64;

    const uint32_t smem_u = s2u(smem);

    // gmem load coords: both tiles are 128 rows x 32 floats (8 f4/row)
    const int rowL = tid >> 3, k4L = tid & 7;    // rows rowL + i*16, i = 0..7
    const float* gA = A  + (size_t)(m0 + rowL) * DD + k4L * 4;
    const float* gB = Wt + (size_t)(n0 + rowL) * DD + k4L * 4;

    // LDSM per-lane offsets (bytes within tile)
    const int q = lane >> 3, e = lane & 7;
    uint32_t aoff[4], boff[4];
#pragma unroll
    for (int mi = 0; mi < 4; mi++)
        aoff[mi] = (uint32_t)((mBase + mi * 16 + e + ((q & 1) << 3)) * TPITCH + ((q >> 1) << 4));
#pragma unroll
    for (int p = 0; p < 4; p++)
        boff[p] = (uint32_t)((nBase + p * 16 + ((q >> 1) << 3) + e) * TPITCH + ((q & 1) << 4));

    float acc[4][8][4];
#pragma unroll
    for (int mi = 0; mi < 4; mi++)
#pragma unroll
        for (int ni = 0; ni < 8; ni++)
#pragma unroll
            for (int i = 0; i < 4; i++) acc[mi][ni][i] = 0.f;

#define LOAD_CHUNK(k0, stage)                                                   \
    {                                                                           \
        const uint32_t sA = smem_u + (stage) * STAGE_BYTES;                     \
        const uint32_t sB = sA + AS_BYTES;                                      \
        _Pragma("unroll")                                                       \
        for (int i = 0; i < 8; i++)                                             \
            CP16(sA + (rowL + i * 16) * TPITCH + k4L * 16,                      \
                 gA + (size_t)(i * 16) * DD + (k0));                            \
        _Pragma("unroll")                                                       \
        for (int i = 0; i < 8; i++)                                             \
            CP16(sB + (rowL + i * 16) * TPITCH + k4L * 16,                      \
                 gB + (size_t)(i * 16) * DD + (k0));                            \
    }

// load fragments for kk byte-offset kb into buffer slot b
#define FRAG_LOAD(b, kb)                                                        \
    {                                                                           \
        _Pragma("unroll")                                                       \
        for (int mi = 0; mi < 4; mi++)                                          \
            LDSM4(af[b][mi][0], af[b][mi][1], af[b][mi][2], af[b][mi][3],       \
                  sA + aoff[mi] + (kb));                                        \
        _Pragma("unroll")                                                       \
        for (int p = 0; p < 4; p++)                                             \
            LDSM4(bf[b][2 * p][0], bf[b][2 * p][1],                             \
                  bf[b][2 * p + 1][0], bf[b][2 * p + 1][1],                     \
                  sB + boff[p] + (kb));                                         \
    }

    LOAD_CHUNK(0, 0);  CP_COMMIT();
    LOAD_CHUNK(32, 1); CP_COMMIT();

    uint32_t af[2][4][4], bf[2][8][2];

    for (int kt = 0; kt < 32; ++kt) {
        if (kt < 31) asm volatile("cp.async.wait_group 1;" ::: "memory");
        else         asm volatile("cp.async.wait_group 0;" ::: "memory");
        __syncthreads();

        const int s = kt % 3;
        const uint32_t sA = smem_u + s * STAGE_BYTES;
        const uint32_t sB = sA + AS_BYTES;

        const bool doPf = (kt + 2 < 32);
        const int pfk0 = (kt + 2) * 32;
        const int pfs = (kt + 2) % 3;
        const uint32_t pA = smem_u + pfs * STAGE_BYTES;
        const uint32_t pB = pA + AS_BYTES;

        FRAG_LOAD(0, 0);

#pragma unroll
        for (int kk8 = 0; kk8 < 4; kk8++) {
            const int cur = kk8 & 1;
            // spread gmem prefetch: 2 A-f4 + 2 B-f4 per thread per kk step
            if (doPf) {
#pragma unroll
                for (int j = 0; j < 2; j++) {
                    const int i = kk8 * 2 + j;
                    CP16(pA + (rowL + i * 16) * TPITCH + k4L * 16,
                         gA + (size_t)(i * 16) * DD + pfk0);
                    CP16(pB + (rowL + i * 16) * TPITCH + k4L * 16,
                         gB + (size_t)(i * 16) * DD + pfk0);
                }
            }
            // prefetch next kk-step fragments into alternate buffer
            if (kk8 < 3) {
                const int nxt = cur ^ 1;
                const uint32_t kbn = (kk8 + 1) * 32;
                FRAG_LOAD(nxt, kbn);
            }
#pragma unroll
            for (int mi = 0; mi < 4; mi++)
#pragma unroll
                for (int ni = 0; ni < 8; ni++)
                    MMA_TF32(acc[mi][ni], af[cur][mi], bf[cur][ni]);
        }
        if (doPf) CP_COMMIT();
    }
#undef LOAD_CHUNK
#undef FRAG_LOAD

    // ---------------- epilogue ----------------
#pragma unroll
    for (int mi = 0; mi < 4; mi++) {
#pragma unroll
        for (int ni = 0; ni < 8; ni++) {
            const int r = m0 + mBase + mi * 16 + g;
            const int c = n0 + nBase + ni * 8 + 2 * tg;
            const float b0 = __ldg(bias + c);
            const float b1 = __ldg(bias + c + 1);
#pragma unroll
            for (int half = 0; half < 2; half++) {
                const int rr = r + half * 8;
                float da = acc[mi][ni][half * 2 + 0] + b0;
                float db = acc[mi][ni][half * 2 + 1] + b1;
                float oa, ob;
                if (EPI == 1) {
                    const float sa = da * sigmoidf_(da);   // silu
                    const float sb = db * sigmoidf_(db);
                    const float2 xv = *(const float2*)(X + (size_t)rr * DD + c);
                    oa = xv.x + sigmoidf_(sa) * da;
                    ob = xv.y + sigmoidf_(sb) * db;
                } else {
                    oa = da; ob = db;
                }
                *(float2*)(C + (size_t)rr * ldc + c) = make_float2(oa, ob);
            }
        }
    }
}

// ---------------- launch ----------------
extern "C" void kernel_launch(void* const* d_in, const int* in_sizes, int n_in,
                              void* d_out, int out_size) {
    const float* x   = (const float*)d_in[0];
    const float* g1  = (const float*)d_in[1];
    const float* Wq  = (const float*)d_in[2];
    const float* bq  = (const float*)d_in[3];
    const float* Wk  = (const float*)d_in[4];
    const float* bk  = (const float*)d_in[5];
    const float* Wv  = (const float*)d_in[6];
    const float* bv  = (const float*)d_in[7];
    const float* wqc = (const float*)d_in[8];
    const float* bqc = (const float*)d_in[9];
    const float* wkc = (const float*)d_in[10];
    const float* bkc = (const float*)d_in[11];
    const float* wvc = (const float*)d_in[12];
    const float* bvc = (const float*)d_in[13];
    const float* Wa  = (const float*)d_in[14];
    const float* ba  = (const float*)d_in[15];
    const float* Wb  = (const float*)d_in[16];
    const float* bb  = (const float*)d_in[17];
    const float* g2  = (const float*)d_in[18];
    const float* Wp  = (const float*)d_in[19];
    const float* bp  = (const float*)d_in[20];
    float* out = (float*)d_out;

    float* sc = nullptr;
    cudaGetSymbolAddress((void**)&sc, g_scratch);
    float* wt = nullptr;
    cudaGetSymbolAddress((void**)&wt, g_wt);
    float* bc = nullptr;
    cudaGetSymbolAddress((void**)&bc, g_bias);

    const size_t SZ = (size_t)NTOK * DD;
    float* h    = sc + 0 * SZ;
    float* qkv  = sc + 1 * SZ;   // [16384, 3072]
    float* abp  = sc + 4 * SZ;   // [16384, 2048]
    float* dn   = sc + 6 * SZ;

    const size_t WSZ = (size_t)DD * DD;
    float* Wqkv_t = wt + 0 * WSZ;
    float* Wab_t  = wt + 3 * WSZ;
    float* Wp_t   = wt + 5 * WSZ;

    cudaFuncSetAttribute(gemm_kernel<0>, cudaFuncAttributeMaxDynamicSharedMemorySize, SMEM_GEMM);
    cudaFuncSetAttribute(gemm_kernel<1>, cudaFuncAttributeMaxDynamicSharedMemorySize, SMEM_GEMM);

    // [1] prep (weight transpose + rna, bias concat)
    prep_kernel<<<dim3(32, 32, 7), dim3(32, 8)>>>(Wq, Wk, Wv, Wa, Wb, Wp,
                                                  bq, bk, bv, ba, bb);

    // [2] zc_rms
    zc_rms_kernel<<<NTOK, 256>>>((const float4*)x, (const float4*)g1, (float4*)h);

    // [3] qkv GEMM  (N = 3072)
    gemm_kernel<0><<<dim3(24, 128), 128, SMEM_GEMM>>>(h, Wqkv_t, bc, nullptr, qkv, 3072);
    // [4] ab GEMM   (N = 2048)
    gemm_kernel<0><<<dim3(16, 128), 128, SMEM_GEMM>>>(x, Wab_t, bc + 3072, nullptr, abp, 2048);

    // [5] fused conv/delta/norm (rolling t-window)
    conv_delta_kernel<<<NTOK / TCHUNK, 256>>>((const float4*)qkv, (const float4*)abp,
                                              wqc, bqc, wkc, bkc, wvc, bvc,
                                              (const float4*)g2, (float4*)dn);

    // [6] final GEMM + residual epilogue
    gemm_kernel<1><<<dim3(8, 128), 128, SMEM_GEMM>>>(dn, Wp_t, bp, x, out, 1024);
}